// round 2
// baseline (speedup 1.0000x reference)
#include <cuda_runtime.h>
#include <math.h>

// Problem constants (fixed by the reference):
#define BATCH 4
#define TLEN  2048
#define DMODEL 1024
#define DINT   1024
#define MTOT  (BATCH * TLEN)     // 8192
#define HALFD (DINT / 2)         // 512

// ---------------------------------------------------------------------------
// Scratch (device globals; no allocation allowed)
// ---------------------------------------------------------------------------
__device__ float g_Q[BATCH * TLEN * DINT];          // 32 MB
__device__ float g_K[BATCH * TLEN * DINT];          // 32 MB
__device__ float g_V[BATCH * TLEN * DINT];          // 32 MB
__device__ float g_S[BATCH * TLEN * TLEN];          // 64 MB (scores -> probs in place)
__device__ float g_invfreq[HALFD];

// ---------------------------------------------------------------------------
// inv_freq table (double precision, rounded to f32 — matches jax f32 pow ~1ulp)
// ---------------------------------------------------------------------------
__global__ void init_freq_kernel() {
    int p = blockIdx.x * blockDim.x + threadIdx.x;
    if (p < HALFD) {
        // inv_freq[p] = 10000^(-(2p)/1024)
        double e = exp(-((double)(2 * p) / (double)DINT) * 9.210340371976184); // ln(10000)
        g_invfreq[p] = (float)e;
    }
}

// ---------------------------------------------------------------------------
// Kernel 1: QKV projection.  C[m,n] = sum_k X[m,k] * W[n,k]
// M = 8192, N = 3072, K = 1024.  "TN" layout: both operands K-contiguous.
// Tile 128x64x16, 256 threads, 8x4 accumulators per thread.
// Writes directly into g_Q / g_K / g_V (N tile of 64 never straddles a boundary).
// ---------------------------------------------------------------------------
__global__ __launch_bounds__(256)
void qkv_gemm_kernel(const float* __restrict__ X, const float* __restrict__ W) {
    constexpr int BM = 128, BN = 64, BK = 16, K = DMODEL;
    __shared__ float As[BK][BM];
    __shared__ float Bs[BK][BN];

    const int tid = threadIdx.x;
    const int tx = tid & 15;        // 0..15  -> N
    const int ty = tid >> 4;        // 0..15  -> M
    const int m0 = blockIdx.y * BM;
    const int n0 = blockIdx.x * BN;

    const int lrow = tid >> 2;       // 0..63
    const int lk4  = (tid & 3) * 4;  // 0,4,8,12

    float acc[8][4] = {};

    for (int k0 = 0; k0 < K; k0 += BK) {
        #pragma unroll
        for (int h = 0; h < 2; ++h) {
            int r = lrow + h * 64;
            float4 v = *(const float4*)&X[(size_t)(m0 + r) * K + k0 + lk4];
            As[lk4 + 0][r] = v.x; As[lk4 + 1][r] = v.y;
            As[lk4 + 2][r] = v.z; As[lk4 + 3][r] = v.w;
        }
        {
            float4 v = *(const float4*)&W[(size_t)(n0 + lrow) * K + k0 + lk4];
            Bs[lk4 + 0][lrow] = v.x; Bs[lk4 + 1][lrow] = v.y;
            Bs[lk4 + 2][lrow] = v.z; Bs[lk4 + 3][lrow] = v.w;
        }
        __syncthreads();
        #pragma unroll
        for (int kk = 0; kk < BK; ++kk) {
            float a[8], b[4];
            *(float4*)&a[0] = *(const float4*)&As[kk][ty * 8];
            *(float4*)&a[4] = *(const float4*)&As[kk][ty * 8 + 4];
            *(float4*)&b[0] = *(const float4*)&Bs[kk][tx * 4];
            #pragma unroll
            for (int i = 0; i < 8; ++i)
                #pragma unroll
                for (int j = 0; j < 4; ++j)
                    acc[i][j] += a[i] * b[j];
        }
        __syncthreads();
    }

    // Route the 64-wide N tile to Q / K / V.
    int ng = n0 + tx * 4;
    float* dst;
    int ncol;
    if (ng < DINT)            { dst = g_Q; ncol = ng; }
    else if (ng < 2 * DINT)   { dst = g_K; ncol = ng - DINT; }
    else                      { dst = g_V; ncol = ng - 2 * DINT; }

    #pragma unroll
    for (int i = 0; i < 8; ++i) {
        int m = m0 + ty * 8 + i;
        float4 v = make_float4(acc[i][0], acc[i][1], acc[i][2], acc[i][3]);
        *(float4*)&dst[(size_t)m * DINT + ncol] = v;
    }
}

// ---------------------------------------------------------------------------
// Kernel 2: RoPE + L2 normalize + per-channel scale, applied to Q and K rows.
// One block per (token, {Q,K}); 256 threads; each thread owns 2 rotation pairs.
// ---------------------------------------------------------------------------
__global__ __launch_bounds__(256)
void rope_norm_kernel(const float* __restrict__ sqk, float sqk_mul) {
    const int token = blockIdx.x;              // 0..8191
    const int tpos = token & (TLEN - 1);
    float* row = (blockIdx.y == 0 ? g_Q : g_K) + (size_t)token * DINT;

    const int tid = threadIdx.x;
    float na[2], nb[2];
    float ss = 0.0f;
    #pragma unroll
    for (int h = 0; h < 2; ++h) {
        int p = tid + h * 256;                 // pair index 0..511
        float a = row[p];
        float b = row[p + HALFD];
        float ang = (float)tpos * g_invfreq[p];
        float s, c;
        sincosf(ang, &s, &c);
        na[h] = a * c - b * s;
        nb[h] = b * c + a * s;
        ss += na[h] * na[h] + nb[h] * nb[h];
    }

    // block-sum ss
    __shared__ float warp_red[8];
    #pragma unroll
    for (int o = 16; o > 0; o >>= 1) ss += __shfl_xor_sync(0xffffffffu, ss, o);
    if ((tid & 31) == 0) warp_red[tid >> 5] = ss;
    __syncthreads();
    __shared__ float total_sh;
    if (tid == 0) {
        float t = 0.0f;
        #pragma unroll
        for (int w = 0; w < 8; ++w) t += warp_red[w];
        total_sh = t;
    }
    __syncthreads();
    float rnorm = 1.0f / sqrtf(total_sh);

    #pragma unroll
    for (int h = 0; h < 2; ++h) {
        int p = tid + h * 256;
        row[p]         = na[h] * rnorm * (sqk[p] * sqk_mul);
        row[p + HALFD] = nb[h] * rnorm * (sqk[p + HALFD] * sqk_mul);
    }
}

// ---------------------------------------------------------------------------
// Kernel 3: S[b,q,k] = scale * sum_d Q[b,q,d] * K[b,k,d]   (causal block skip)
// Same TN tiling as kernel 1.  grid = (kTiles=32, qTiles=16, B=4)
// ---------------------------------------------------------------------------
__global__ __launch_bounds__(256)
void qk_gemm_kernel(float scale) {
    constexpr int BM = 128, BN = 64, BK = 16, K = DINT;
    const int b  = blockIdx.z;
    const int q0 = blockIdx.y * BM;
    const int k0n = blockIdx.x * BN;
    if (k0n >= q0 + BM) return;    // fully above the diagonal -> never read

    const float* A  = g_Q + (size_t)b * TLEN * DINT;
    const float* Bm = g_K + (size_t)b * TLEN * DINT;
    float* S        = g_S + (size_t)b * TLEN * TLEN;

    __shared__ float As[BK][BM];
    __shared__ float Bs[BK][BN];
    const int tid = threadIdx.x;
    const int tx = tid & 15, ty = tid >> 4;
    const int lrow = tid >> 2;
    const int lk4  = (tid & 3) * 4;

    float acc[8][4] = {};

    for (int k0 = 0; k0 < K; k0 += BK) {
        #pragma unroll
        for (int h = 0; h < 2; ++h) {
            int r = lrow + h * 64;
            float4 v = *(const float4*)&A[(size_t)(q0 + r) * K + k0 + lk4];
            As[lk4 + 0][r] = v.x; As[lk4 + 1][r] = v.y;
            As[lk4 + 2][r] = v.z; As[lk4 + 3][r] = v.w;
        }
        {
            float4 v = *(const float4*)&Bm[(size_t)(k0n + lrow) * K + k0 + lk4];
            Bs[lk4 + 0][lrow] = v.x; Bs[lk4 + 1][lrow] = v.y;
            Bs[lk4 + 2][lrow] = v.z; Bs[lk4 + 3][lrow] = v.w;
        }
        __syncthreads();
        #pragma unroll
        for (int kk = 0; kk < BK; ++kk) {
            float a[8], bq[4];
            *(float4*)&a[0] = *(const float4*)&As[kk][ty * 8];
            *(float4*)&a[4] = *(const float4*)&As[kk][ty * 8 + 4];
            *(float4*)&bq[0] = *(const float4*)&Bs[kk][tx * 4];
            #pragma unroll
            for (int i = 0; i < 8; ++i)
                #pragma unroll
                for (int j = 0; j < 4; ++j)
                    acc[i][j] += a[i] * bq[j];
        }
        __syncthreads();
    }

    const int kc = k0n + tx * 4;
    #pragma unroll
    for (int i = 0; i < 8; ++i) {
        int q = q0 + ty * 8 + i;
        float4 v = make_float4(acc[i][0] * scale, acc[i][1] * scale,
                               acc[i][2] * scale, acc[i][3] * scale);
        *(float4*)&S[(size_t)q * TLEN + kc] = v;
    }
}

// ---------------------------------------------------------------------------
// Kernel 4: causal softmax per row, in place on g_S. Writes EXACT zeros for
// k > q so the PV GEMM can run unmasked up to its tile's causal k-limit.
// One block per (q, b); 256 threads x 8 elems.
// ---------------------------------------------------------------------------
__global__ __launch_bounds__(256)
void softmax_kernel() {
    const int q = blockIdx.x;
    const int b = blockIdx.y;
    float* row = g_S + ((size_t)b * TLEN + q) * TLEN;
    const int tid = threadIdx.x;

    float vals[8];
    float m = -INFINITY;
    #pragma unroll
    for (int i = 0; i < 8; ++i) {
        int k = i * 256 + tid;
        float v = (k <= q) ? row[k] : -INFINITY;
        vals[i] = v;
        m = fmaxf(m, v);
    }

    __shared__ float warp_red[8];
    __shared__ float bcast;
    #pragma unroll
    for (int o = 16; o > 0; o >>= 1) m = fmaxf(m, __shfl_xor_sync(0xffffffffu, m, o));
    if ((tid & 31) == 0) warp_red[tid >> 5] = m;
    __syncthreads();
    if (tid == 0) {
        float t = warp_red[0];
        #pragma unroll
        for (int w = 1; w < 8; ++w) t = fmaxf(t, warp_red[w]);
        bcast = t;
    }
    __syncthreads();
    const float rowmax = bcast;

    float sum = 0.0f;
    #pragma unroll
    for (int i = 0; i < 8; ++i) {
        int k = i * 256 + tid;
        float e = (k <= q) ? expf(vals[i] - rowmax) : 0.0f;
        vals[i] = e;
        sum += e;
    }
    #pragma unroll
    for (int o = 16; o > 0; o >>= 1) sum += __shfl_xor_sync(0xffffffffu, sum, o);
    if ((tid & 31) == 0) warp_red[tid >> 5] = sum;
    __syncthreads();
    if (tid == 0) {
        float t = 0.0f;
        #pragma unroll
        for (int w = 0; w < 8; ++w) t += warp_red[w];
        bcast = t;
    }
    __syncthreads();
    const float inv = 1.0f / bcast;

    #pragma unroll
    for (int i = 0; i < 8; ++i) {
        int k = i * 256 + tid;
        row[k] = vals[i] * inv;
    }
}

// ---------------------------------------------------------------------------
// Kernel 5: O[b,q,n] = sum_k P[b,q,k] * V[b,k,n]   ("NN" layout)
// k-loop bounded by the causal limit of the q tile (P is exact-zero above diag).
// grid = (nTiles=16, qTiles=16, B=4)
// ---------------------------------------------------------------------------
__global__ __launch_bounds__(256)
void pv_gemm_kernel(float* __restrict__ out) {
    constexpr int BM = 128, BN = 64, BK = 16;
    const int b  = blockIdx.z;
    const int q0 = blockIdx.y * BM;
    const int n0 = blockIdx.x * BN;
    const float* P = g_S + (size_t)b * TLEN * TLEN;   // [TLEN, TLEN]
    const float* V = g_V + (size_t)b * TLEN * DINT;   // [TLEN, DINT]
    const int kmax = q0 + BM;                         // causal limit for this q tile

    __shared__ float As[BK][BM];
    __shared__ float Bs[BK][BN];
    const int tid = threadIdx.x;
    const int tx = tid & 15, ty = tid >> 4;
    const int lrow = tid >> 2;         // A-tile: 0..63
    const int lk4  = (tid & 3) * 4;
    const int brow = tid >> 4;         // B-tile: 0..15
    const int bc4  = (tid & 15) * 4;

    float acc[8][4] = {};

    for (int k0 = 0; k0 < kmax; k0 += BK) {
        #pragma unroll
        for (int h = 0; h < 2; ++h) {
            int r = lrow + h * 64;
            float4 v = *(const float4*)&P[(size_t)(q0 + r) * TLEN + k0 + lk4];
            As[lk4 + 0][r] = v.x; As[lk4 + 1][r] = v.y;
            As[lk4 + 2][r] = v.z; As[lk4 + 3][r] = v.w;
        }
        {
            float4 v = *(const float4*)&V[(size_t)(k0 + brow) * DINT + n0 + bc4];
            *(float4*)&Bs[brow][bc4] = v;
        }
        __syncthreads();
        #pragma unroll
        for (int kk = 0; kk < BK; ++kk) {
            float a[8], bq[4];
            *(float4*)&a[0] = *(const float4*)&As[kk][ty * 8];
            *(float4*)&a[4] = *(const float4*)&As[kk][ty * 8 + 4];
            *(float4*)&bq[0] = *(const float4*)&Bs[kk][tx * 4];
            #pragma unroll
            for (int i = 0; i < 8; ++i)
                #pragma unroll
                for (int j = 0; j < 4; ++j)
                    acc[i][j] += a[i] * bq[j];
        }
        __syncthreads();
    }

    const int nc = n0 + tx * 4;
    #pragma unroll
    for (int i = 0; i < 8; ++i) {
        int q = q0 + ty * 8 + i;
        float4 v = make_float4(acc[i][0], acc[i][1], acc[i][2], acc[i][3]);
        *(float4*)&out[((size_t)(b * TLEN + q)) * DINT + nc] = v;
    }
}

// ---------------------------------------------------------------------------
// Launch
// ---------------------------------------------------------------------------
extern "C" void kernel_launch(void* const* d_in, const int* in_sizes, int n_in,
                              void* d_out, int out_size) {
    (void)n_in; (void)out_size; (void)in_sizes;
    const float* input_vecs = (const float*)d_in[0];   // [B, T, DMODEL]
    const float* qkv_w      = (const float*)d_in[1];   // [3*DINT, DMODEL]
    const float* sqk        = (const float*)d_in[2];   // [DINT]
    float* out              = (float*)d_out;           // [B, T, DINT]

    const float sqk_mul = sqrtf((float)DMODEL);        // 32: sqk_eff = sqk * sqrt(d_model)
    const float scale   = sqrtf((float)DMODEL);        // SDPA scale = sqrt(d_model)

    init_freq_kernel<<<2, 256>>>();

    qkv_gemm_kernel<<<dim3(3 * DINT / 64, MTOT / 128), 256>>>(input_vecs, qkv_w);

    rope_norm_kernel<<<dim3(MTOT, 2), 256>>>(sqk, sqk_mul);

    qk_gemm_kernel<<<dim3(TLEN / 64, TLEN / 128, BATCH), 256>>>(scale);

    softmax_kernel<<<dim3(TLEN, BATCH), 256>>>();

    pv_gemm_kernel<<<dim3(DINT / 64, TLEN / 128, BATCH), 256>>>(out);
}

// round 3
// speedup vs baseline: 2.1193x; 2.1193x over previous
#include <cuda_runtime.h>
#include <cuda_bf16.h>
#include <math.h>

#define BATCH 4
#define TLEN  2048
#define DMODEL 1024
#define DINT   1024
#define MTOT  (BATCH * TLEN)     // 8192
#define HALFD (DINT / 2)         // 512

// ---------------------------------------------------------------------------
// Scratch (device globals; no allocation allowed)
// ---------------------------------------------------------------------------
__device__ float g_Q[MTOT * DINT];
__device__ float g_K[MTOT * DINT];
__device__ float g_V[MTOT * DINT];
__device__ float g_S[BATCH * TLEN * TLEN];
__device__ float g_invfreq[HALFD];

// ---------------------------------------------------------------------------
// Helpers: ldmatrix / mma / f32 -> bf16 hi+lo split
// ---------------------------------------------------------------------------
__device__ __forceinline__ unsigned smem_u32(const void* p) {
    return (unsigned)__cvta_generic_to_shared(p);
}
__device__ __forceinline__ void ldm_x4(unsigned a, unsigned& r0, unsigned& r1,
                                       unsigned& r2, unsigned& r3) {
    asm volatile("ldmatrix.sync.aligned.m8n8.x4.shared.b16 {%0,%1,%2,%3}, [%4];"
                 : "=r"(r0), "=r"(r1), "=r"(r2), "=r"(r3) : "r"(a));
}
__device__ __forceinline__ void ldm_x4_t(unsigned a, unsigned& r0, unsigned& r1,
                                         unsigned& r2, unsigned& r3) {
    asm volatile("ldmatrix.sync.aligned.m8n8.x4.trans.shared.b16 {%0,%1,%2,%3}, [%4];"
                 : "=r"(r0), "=r"(r1), "=r"(r2), "=r"(r3) : "r"(a));
}
__device__ __forceinline__ void mma16816(float* c, const unsigned* a,
                                         unsigned b0, unsigned b1) {
    asm volatile("mma.sync.aligned.m16n8k16.row.col.f32.bf16.bf16.f32 "
                 "{%0,%1,%2,%3}, {%4,%5,%6,%7}, {%8,%9}, {%0,%1,%2,%3};"
                 : "+f"(c[0]), "+f"(c[1]), "+f"(c[2]), "+f"(c[3])
                 : "r"(a[0]), "r"(a[1]), "r"(a[2]), "r"(a[3]), "r"(b0), "r"(b1));
}
// Split 4 f32 into bf16 hi + bf16 lo and store into padded smem tiles.
__device__ __forceinline__ void split_store4(__nv_bfloat16* hi, __nv_bfloat16* lo,
                                             int off, float4 v) {
    __nv_bfloat16 h0 = __float2bfloat16_rn(v.x);
    __nv_bfloat16 h1 = __float2bfloat16_rn(v.y);
    __nv_bfloat16 h2 = __float2bfloat16_rn(v.z);
    __nv_bfloat16 h3 = __float2bfloat16_rn(v.w);
    __nv_bfloat162 hp0; hp0.x = h0; hp0.y = h1;
    __nv_bfloat162 hp1; hp1.x = h2; hp1.y = h3;
    *(__nv_bfloat162*)&hi[off]     = hp0;
    *(__nv_bfloat162*)&hi[off + 2] = hp1;
    __nv_bfloat162 lp0, lp1;
    lp0.x = __float2bfloat16_rn(v.x - __bfloat162float(h0));
    lp0.y = __float2bfloat16_rn(v.y - __bfloat162float(h1));
    lp1.x = __float2bfloat16_rn(v.z - __bfloat162float(h2));
    lp1.y = __float2bfloat16_rn(v.w - __bfloat162float(h3));
    *(__nv_bfloat162*)&lo[off]     = lp0;
    *(__nv_bfloat162*)&lo[off + 2] = lp1;
}

// ---------------------------------------------------------------------------
// TN GEMM core: acc += A[m0..+128, k] * B[n0..+64, k]^T over k in [kbeg,kend).
// Both operands K-contiguous. 256 threads, warp grid 4(M) x 2(N).
// smem tiles: A [128][40] halfs (32 used + 8 pad), B [64][40].
// Each warp: 2 m-frags x 4 n-frags of m16n8k16; 3 MMAs (hh, hl, lh) per frag.
// ---------------------------------------------------------------------------
__device__ __forceinline__ void tn_gemm_acc(
    const float* __restrict__ A, int strideA,
    const float* __restrict__ B, int strideB,
    int m0, int n0, int kbeg, int kend,
    __nv_bfloat16* sAhi, __nv_bfloat16* sAlo,
    __nv_bfloat16* sBhi, __nv_bfloat16* sBlo,
    float acc[2][4][4])
{
    const int tid = threadIdx.x, lane = tid & 31, warp = tid >> 5;
    const int wm = warp & 3, wn = warp >> 2;
    const int lr = (lane & 7) + ((lane >> 3) & 1) * 8;
    const int lc8 = (lane >> 4) * 8;

    for (int k0 = kbeg; k0 < kend; k0 += 32) {
        #pragma unroll
        for (int i = 0; i < 4; ++i) {               // A: 128 x 32 f32
            int idx = i * 256 + tid;
            int r = idx >> 3, c4 = (idx & 7) * 4;
            float4 v = *(const float4*)&A[(size_t)(m0 + r) * strideA + k0 + c4];
            split_store4(sAhi, sAlo, r * 40 + c4, v);
        }
        #pragma unroll
        for (int i = 0; i < 2; ++i) {               // B: 64 x 32 f32
            int idx = i * 256 + tid;
            int r = idx >> 3, c4 = (idx & 7) * 4;
            float4 v = *(const float4*)&B[(size_t)(n0 + r) * strideB + k0 + c4];
            split_store4(sBhi, sBlo, r * 40 + c4, v);
        }
        __syncthreads();
        #pragma unroll
        for (int ks = 0; ks < 2; ++ks) {
            const int kb = ks * 16 + lc8;
            unsigned ah[2][4], al[2][4], bh[2][4], bl[2][4];
            #pragma unroll
            for (int mf = 0; mf < 2; ++mf) {
                int row = wm * 32 + mf * 16 + lr;
                ldm_x4(smem_u32(&sAhi[row * 40 + kb]), ah[mf][0], ah[mf][1], ah[mf][2], ah[mf][3]);
                ldm_x4(smem_u32(&sAlo[row * 40 + kb]), al[mf][0], al[mf][1], al[mf][2], al[mf][3]);
            }
            #pragma unroll
            for (int g = 0; g < 2; ++g) {
                int row = wn * 32 + g * 16 + lr;
                ldm_x4(smem_u32(&sBhi[row * 40 + kb]), bh[g][0], bh[g][1], bh[g][2], bh[g][3]);
                ldm_x4(smem_u32(&sBlo[row * 40 + kb]), bl[g][0], bl[g][1], bl[g][2], bl[g][3]);
            }
            #pragma unroll
            for (int mf = 0; mf < 2; ++mf)
                #pragma unroll
                for (int nf = 0; nf < 4; ++nf) {
                    int g = nf >> 1, s = nf & 1;
                    mma16816(acc[mf][nf], ah[mf], bh[g][s], bh[g][s + 2]);
                    mma16816(acc[mf][nf], ah[mf], bl[g][s], bl[g][s + 2]);
                    mma16816(acc[mf][nf], al[mf], bh[g][s], bh[g][s + 2]);
                }
        }
        __syncthreads();
    }
}

// ---------------------------------------------------------------------------
// inv_freq table
// ---------------------------------------------------------------------------
__global__ void init_freq_kernel() {
    int p = blockIdx.x * blockDim.x + threadIdx.x;
    if (p < HALFD) {
        double e = exp(-((double)(2 * p) / (double)DINT) * 9.210340371976184);
        g_invfreq[p] = (float)e;
    }
}

// ---------------------------------------------------------------------------
// Kernel 1: QKV projection (tensor cores). M=8192, N=3072, K=1024.
// ---------------------------------------------------------------------------
__global__ __launch_bounds__(256)
void qkv_gemm_tc(const float* __restrict__ X, const float* __restrict__ W) {
    __shared__ __nv_bfloat16 sAhi[128 * 40], sAlo[128 * 40];
    __shared__ __nv_bfloat16 sBhi[64 * 40],  sBlo[64 * 40];
    const int m0 = blockIdx.y * 128, n0 = blockIdx.x * 64;
    float acc[2][4][4] = {};
    tn_gemm_acc(X, DMODEL, W, DMODEL, m0, n0, 0, DMODEL, sAhi, sAlo, sBhi, sBlo, acc);

    const int tid = threadIdx.x, lane = tid & 31, warp = tid >> 5;
    const int wm = warp & 3, wn = warp >> 2;
    float* dst; int nb;
    if (n0 < DINT)            { dst = g_Q; nb = n0; }
    else if (n0 < 2 * DINT)   { dst = g_K; nb = n0 - DINT; }
    else                      { dst = g_V; nb = n0 - 2 * DINT; }
    #pragma unroll
    for (int mf = 0; mf < 2; ++mf)
        #pragma unroll
        for (int nf = 0; nf < 4; ++nf) {
            int r = m0 + wm * 32 + mf * 16 + (lane >> 2);
            int c = nb + wn * 32 + nf * 8 + (lane & 3) * 2;
            *(float2*)&dst[(size_t)r * DINT + c]       = make_float2(acc[mf][nf][0], acc[mf][nf][1]);
            *(float2*)&dst[(size_t)(r + 8) * DINT + c] = make_float2(acc[mf][nf][2], acc[mf][nf][3]);
        }
}

// ---------------------------------------------------------------------------
// Kernel 2: RoPE + L2 norm + scale (unchanged)
// ---------------------------------------------------------------------------
__global__ __launch_bounds__(256)
void rope_norm_kernel(const float* __restrict__ sqk, float sqk_mul) {
    const int token = blockIdx.x;
    const int tpos = token & (TLEN - 1);
    float* row = (blockIdx.y == 0 ? g_Q : g_K) + (size_t)token * DINT;

    const int tid = threadIdx.x;
    float na[2], nb[2];
    float ss = 0.0f;
    #pragma unroll
    for (int h = 0; h < 2; ++h) {
        int p = tid + h * 256;
        float a = row[p];
        float b = row[p + HALFD];
        float ang = (float)tpos * g_invfreq[p];
        float s, c;
        sincosf(ang, &s, &c);
        na[h] = a * c - b * s;
        nb[h] = b * c + a * s;
        ss += na[h] * na[h] + nb[h] * nb[h];
    }
    __shared__ float warp_red[8];
    #pragma unroll
    for (int o = 16; o > 0; o >>= 1) ss += __shfl_xor_sync(0xffffffffu, ss, o);
    if ((tid & 31) == 0) warp_red[tid >> 5] = ss;
    __syncthreads();
    __shared__ float total_sh;
    if (tid == 0) {
        float t = 0.0f;
        #pragma unroll
        for (int w = 0; w < 8; ++w) t += warp_red[w];
        total_sh = t;
    }
    __syncthreads();
    float rnorm = 1.0f / sqrtf(total_sh);
    #pragma unroll
    for (int h = 0; h < 2; ++h) {
        int p = tid + h * 256;
        row[p]         = na[h] * rnorm * (sqk[p] * sqk_mul);
        row[p + HALFD] = nb[h] * rnorm * (sqk[p + HALFD] * sqk_mul);
    }
}

// ---------------------------------------------------------------------------
// Kernel 3: scores S = scale * Q K^T (tensor cores, causal block skip)
// ---------------------------------------------------------------------------
__global__ __launch_bounds__(256)
void qk_gemm_tc(float scale) {
    const int b  = blockIdx.z;
    const int q0 = blockIdx.y * 128;
    const int k0n = blockIdx.x * 64;
    if (k0n >= q0 + 128) return;

    __shared__ __nv_bfloat16 sAhi[128 * 40], sAlo[128 * 40];
    __shared__ __nv_bfloat16 sBhi[64 * 40],  sBlo[64 * 40];
    const float* Qb = g_Q + (size_t)b * TLEN * DINT;
    const float* Kb = g_K + (size_t)b * TLEN * DINT;
    float* S        = g_S + (size_t)b * TLEN * TLEN;

    float acc[2][4][4] = {};
    tn_gemm_acc(Qb, DINT, Kb, DINT, q0, k0n, 0, DINT, sAhi, sAlo, sBhi, sBlo, acc);

    const int tid = threadIdx.x, lane = tid & 31, warp = tid >> 5;
    const int wm = warp & 3, wn = warp >> 2;
    #pragma unroll
    for (int mf = 0; mf < 2; ++mf)
        #pragma unroll
        for (int nf = 0; nf < 4; ++nf) {
            int q = q0 + wm * 32 + mf * 16 + (lane >> 2);
            int c = k0n + wn * 32 + nf * 8 + (lane & 3) * 2;
            *(float2*)&S[(size_t)q * TLEN + c] =
                make_float2(acc[mf][nf][0] * scale, acc[mf][nf][1] * scale);
            *(float2*)&S[(size_t)(q + 8) * TLEN + c] =
                make_float2(acc[mf][nf][2] * scale, acc[mf][nf][3] * scale);
        }
}

// ---------------------------------------------------------------------------
// Kernel 4: causal softmax (unchanged; writes exact zeros above diagonal)
// ---------------------------------------------------------------------------
__global__ __launch_bounds__(256)
void softmax_kernel() {
    const int q = blockIdx.x;
    const int b = blockIdx.y;
    float* row = g_S + ((size_t)b * TLEN + q) * TLEN;
    const int tid = threadIdx.x;

    float vals[8];
    float m = -INFINITY;
    #pragma unroll
    for (int i = 0; i < 8; ++i) {
        int k = i * 256 + tid;
        float v = (k <= q) ? row[k] : -INFINITY;
        vals[i] = v;
        m = fmaxf(m, v);
    }
    __shared__ float warp_red[8];
    __shared__ float bcast;
    #pragma unroll
    for (int o = 16; o > 0; o >>= 1) m = fmaxf(m, __shfl_xor_sync(0xffffffffu, m, o));
    if ((tid & 31) == 0) warp_red[tid >> 5] = m;
    __syncthreads();
    if (tid == 0) {
        float t = warp_red[0];
        #pragma unroll
        for (int w = 1; w < 8; ++w) t = fmaxf(t, warp_red[w]);
        bcast = t;
    }
    __syncthreads();
    const float rowmax = bcast;

    float sum = 0.0f;
    #pragma unroll
    for (int i = 0; i < 8; ++i) {
        int k = i * 256 + tid;
        float e = (k <= q) ? expf(vals[i] - rowmax) : 0.0f;
        vals[i] = e;
        sum += e;
    }
    #pragma unroll
    for (int o = 16; o > 0; o >>= 1) sum += __shfl_xor_sync(0xffffffffu, sum, o);
    if ((tid & 31) == 0) warp_red[tid >> 5] = sum;
    __syncthreads();
    if (tid == 0) {
        float t = 0.0f;
        #pragma unroll
        for (int w = 0; w < 8; ++w) t += warp_red[w];
        bcast = t;
    }
    __syncthreads();
    const float inv = 1.0f / bcast;
    #pragma unroll
    for (int i = 0; i < 8; ++i) {
        int k = i * 256 + tid;
        row[k] = vals[i] * inv;
    }
}

// ---------------------------------------------------------------------------
// Kernel 5: O = P V (tensor cores).  P [q][k] k-contig (A, non-trans),
// V [k][n] n-contig (B via ldmatrix .trans). k-loop causal-bounded.
// ---------------------------------------------------------------------------
__global__ __launch_bounds__(256)
void pv_gemm_tc(float* __restrict__ out) {
    const int b  = blockIdx.z;
    const int q0 = blockIdx.y * 128;
    const int n0 = blockIdx.x * 64;
    const float* P = g_S + (size_t)b * TLEN * TLEN;
    const float* V = g_V + (size_t)b * TLEN * DINT;
    const int kmax = q0 + 128;

    __shared__ __nv_bfloat16 sPhi[128 * 40], sPlo[128 * 40];
    __shared__ __nv_bfloat16 sVhi[32 * 72],  sVlo[32 * 72];

    const int tid = threadIdx.x, lane = tid & 31, warp = tid >> 5;
    const int wm = warp & 3, wn = warp >> 2;
    const int lrA = (lane & 7) + ((lane >> 3) & 1) * 8;
    const int lcA8 = (lane >> 4) * 8;
    const int lrV = (lane & 7) + ((lane >> 4) & 1) * 8;   // k within tile
    const int lcV8 = ((lane >> 3) & 1) * 8;               // n offset

    float acc[2][4][4] = {};

    for (int k0 = 0; k0 < kmax; k0 += 32) {
        #pragma unroll
        for (int i = 0; i < 4; ++i) {               // P: 128 x 32
            int idx = i * 256 + tid;
            int r = idx >> 3, c4 = (idx & 7) * 4;
            float4 v = *(const float4*)&P[(size_t)(q0 + r) * TLEN + k0 + c4];
            split_store4(sPhi, sPlo, r * 40 + c4, v);
        }
        #pragma unroll
        for (int i = 0; i < 2; ++i) {               // V: 32 x 64
            int idx = i * 256 + tid;
            int r = idx >> 4, c4 = (idx & 15) * 4;
            float4 v = *(const float4*)&V[(size_t)(k0 + r) * DINT + n0 + c4];
            split_store4(sVhi, sVlo, r * 72 + c4, v);
        }
        __syncthreads();
        #pragma unroll
        for (int ks = 0; ks < 2; ++ks) {
            const int kbA = ks * 16 + lcA8;
            const int kbV = ks * 16 + lrV;
            unsigned ah[2][4], al[2][4], bh[2][4], bl[2][4];
            #pragma unroll
            for (int mf = 0; mf < 2; ++mf) {
                int row = wm * 32 + mf * 16 + lrA;
                ldm_x4(smem_u32(&sPhi[row * 40 + kbA]), ah[mf][0], ah[mf][1], ah[mf][2], ah[mf][3]);
                ldm_x4(smem_u32(&sPlo[row * 40 + kbA]), al[mf][0], al[mf][1], al[mf][2], al[mf][3]);
            }
            #pragma unroll
            for (int g = 0; g < 2; ++g) {
                int col = wn * 32 + g * 16 + lcV8;
                ldm_x4_t(smem_u32(&sVhi[kbV * 72 + col]), bh[g][0], bh[g][1], bh[g][2], bh[g][3]);
                ldm_x4_t(smem_u32(&sVlo[kbV * 72 + col]), bl[g][0], bl[g][1], bl[g][2], bl[g][3]);
            }
            #pragma unroll
            for (int mf = 0; mf < 2; ++mf)
                #pragma unroll
                for (int nf = 0; nf < 4; ++nf) {
                    int g = nf >> 1, s = nf & 1;
                    mma16816(acc[mf][nf], ah[mf], bh[g][s], bh[g][s + 2]);
                    mma16816(acc[mf][nf], ah[mf], bl[g][s], bl[g][s + 2]);
                    mma16816(acc[mf][nf], al[mf], bh[g][s], bh[g][s + 2]);
                }
        }
        __syncthreads();
    }

    #pragma unroll
    for (int mf = 0; mf < 2; ++mf)
        #pragma unroll
        for (int nf = 0; nf < 4; ++nf) {
            int q = q0 + wm * 32 + mf * 16 + (lane >> 2);
            int c = n0 + wn * 32 + nf * 8 + (lane & 3) * 2;
            *(float2*)&out[((size_t)(b * TLEN + q)) * DINT + c] =
                make_float2(acc[mf][nf][0], acc[mf][nf][1]);
            *(float2*)&out[((size_t)(b * TLEN + q + 8)) * DINT + c] =
                make_float2(acc[mf][nf][2], acc[mf][nf][3]);
        }
}

// ---------------------------------------------------------------------------
// Launch
// ---------------------------------------------------------------------------
extern "C" void kernel_launch(void* const* d_in, const int* in_sizes, int n_in,
                              void* d_out, int out_size) {
    (void)n_in; (void)out_size; (void)in_sizes;
    const float* input_vecs = (const float*)d_in[0];
    const float* qkv_w      = (const float*)d_in[1];
    const float* sqk        = (const float*)d_in[2];
    float* out              = (float*)d_out;

    const float sqk_mul = sqrtf((float)DMODEL);
    const float scale   = sqrtf((float)DMODEL);

    init_freq_kernel<<<2, 256>>>();

    qkv_gemm_tc<<<dim3(3 * DINT / 64, MTOT / 128), 256>>>(input_vecs, qkv_w);

    rope_norm_kernel<<<dim3(MTOT, 2), 256>>>(sqk, sqk_mul);

    qk_gemm_tc<<<dim3(TLEN / 64, TLEN / 128, BATCH), 256>>>(scale);

    softmax_kernel<<<dim3(TLEN, BATCH), 256>>>();

    pv_gemm_tc<<<dim3(DINT / 64, TLEN / 128, BATCH), 256>>>(out);
}